// round 16
// baseline (speedup 1.0000x reference)
#include <cuda_runtime.h>
#include <math.h>

#define LOG8 2.0794415416798357f
#define NTHREADS 256
#define JTILE 1024   // j-elements per block (256 threads x 4)
#define ITERS 16     // i-rows per block

// SMEM staging tile (floats): [dxyz: 3*JTILE][bkt: JTILE][dsc: JTILE][msk: JTILE]
#define TILE_F (6 * JTILE)   // 6144 floats = 24 KB

__device__ __forceinline__ float bucket_base(float d) {
    float x  = d * 2.0f;              // d / RES, exact
    float ax = fabsf(x);
    float r;
    if (ax <= 2.0f) {
        r = rintf(x);                 // jnp.round = half-to-even
    } else {
        float lr  = __fdiv_rn(logf(__fmul_rn(ax, 0.5f)), LOG8);
        float sup = fminf(rintf(__fsub_rn(2.0f, __fmul_rn(6.0f, lr))), 8.0f);
        r = (x > 0.0f) ? sup : -sup;
    }
    return 8.0f + r;
}

__device__ __forceinline__ unsigned smem_u32(const void* p) {
    return (unsigned)__cvta_generic_to_shared(p);
}

__global__ __launch_bounds__(NTHREADS)
void pair_kernel(const float* __restrict__ xyz, const int* __restrict__ grid,
                 float* __restrict__ out, int N) {
    __shared__ float  sbuf[2][TILE_F];    // 2 x 24 KB staging (prologue scratch too)
    __shared__ float4 s_ipt[ITERS];       // packed i-rows: x,y,z,w1bits
    __shared__ int    s_iw2[ITERS];       // packed i-rows: w2

    const int t     = threadIdx.x;
    const int jbase = blockIdx.x * JTILE;
    const int i0    = blockIdx.y * ITERS;

    // ========= PROLOGUE: coalesced raw staging + pack (replaces pack_kernel) =========
    {
        // raw xyz of j-tile: JTILE*3 floats = 12 KB -> sbuf[0]
        const float4* gx = reinterpret_cast<const float4*>(xyz + (size_t)jbase * 3);
        float4* sx = reinterpret_cast<float4*>(&sbuf[0][0]);
#pragma unroll
        for (int q = 0; q < (JTILE * 3 / 4) / NTHREADS; q++)   // 3 iters
            sx[t + q * NTHREADS] = __ldg(gx + t + q * NTHREADS);

        // raw grid of j-tile: JTILE*5 ints = 20 KB -> sbuf[1]
        const int4* gg = reinterpret_cast<const int4*>(grid + (size_t)jbase * 5);
        int4* sg = reinterpret_cast<int4*>(&sbuf[1][0]);
#pragma unroll
        for (int q = 0; q < (JTILE * 5 / 4) / NTHREADS; q++)   // 5 iters
            sg[t + q * NTHREADS] = __ldg(gg + t + q * NTHREADS);

        // pack the block's 16 i-rows (tiny, scalar)
        if (t < ITERS) {
            const int i = i0 + t;
            const float x = __ldg(xyz + (size_t)i * 3 + 0);
            const float y = __ldg(xyz + (size_t)i * 3 + 1);
            const float z = __ldg(xyz + (size_t)i * 3 + 2);
            const int b  = __ldg(grid + (size_t)i * 5 + 0);
            const int bl = __ldg(grid + (size_t)i * 5 + 1);
            const int c0 = __ldg(grid + (size_t)i * 5 + 2);
            const int c1 = __ldg(grid + (size_t)i * 5 + 3);
            const int c2 = __ldg(grid + (size_t)i * 5 + 4);
            const int cx = (int)ceilf(__fdiv_rn(x, 3.0f));
            const int cy = (int)ceilf(__fdiv_rn(y, 3.0f));
            s_ipt[t] = make_float4(x, y, z,
                                   __int_as_float((bl << 24) | (c2 << 16) | (c1 << 8) | c0));
            s_iw2[t] = (b << 16) | (cy << 8) | cx;
        }
    }
    __syncthreads();

    // pack this thread's 4 j-points from SMEM into registers (once per block)
    float qjx[4], qjy[4], qjz[4];
    int w1j[4], w2j[4], blj[4];
    {
        const float* sx = &sbuf[0][0];
        const int*   sg = reinterpret_cast<const int*>(&sbuf[1][0]);
#pragma unroll
        for (int p = 0; p < 4; p++) {
            const int jl = t * 4 + p;
            qjx[p] = sx[jl * 3 + 0];
            qjy[p] = sx[jl * 3 + 1];
            qjz[p] = sx[jl * 3 + 2];
            const int b  = sg[jl * 5 + 0];
            const int bl = sg[jl * 5 + 1];
            const int c0 = sg[jl * 5 + 2];
            const int c1 = sg[jl * 5 + 3];
            const int c2 = sg[jl * 5 + 4];
            const int cx = (int)ceilf(__fdiv_rn(qjx[p], 3.0f));
            const int cy = (int)ceilf(__fdiv_rn(qjy[p], 3.0f));
            w1j[p] = (bl << 24) | (c2 << 16) | (c1 << 8) | c0;
            w2j[p] = (b << 16) | (cy << 8) | cx;
            blj[p] = bl;
        }
    }
    __syncthreads();   // raw staging consumed; buffers free for the main loop

    // ================= MAIN LOOP (identical to R8 best) =================
    const size_t NN = (size_t)N * (size_t)N;

    for (int k = 0; k < ITERS; k++) {
        const int i = i0 + k;
        float* sb = sbuf[k & 1];

        // per-i data: LDS broadcast
        const float4 qi  = s_ipt[k];
        const int    w1i = __float_as_int(qi.w);
        const int    w2i = s_iw2[k];
        const int    bli = ((unsigned)w1i) >> 24;
        const int    sci = bli >> 1;

        float dxv[12];
        float bkt[4], dsc[4], msk[4];

#pragma unroll
        for (int p = 0; p < 4; p++) {
            const float dx = qi.x - qjx[p];
            const float dy = qi.y - qjy[p];
            const float dz = qi.z - qjz[p];

            const unsigned d1 = __vabsdiffu4(w1i, w1j[p]);  // [c0d,c1d,c2d,bld]
            const unsigned d2 = __vabsdiffu4(w2i, w2j[p]);  // [cxd,cyd,bd,0]

            bool m = ((d2 & 0x00FF0000u) == 0u) && (bli <= blj[p]);
            if (m) {
                const bool fk = (d1 & 0xFFFEFEFEu) == 0u;
                if (!fk) {
                    const bool kc = (d2 & 0x0000FEFEu) == 0u;
                    const float r2 = __fadd_rn(__fadd_rn(__fmul_rn(dx, dx),
                                                         __fmul_rn(dy, dy)),
                                               __fmul_rn(dz, dz));
                    m = kc && (r2 <= 9.0f);
                }
            }

            if (m) {
                dxv[p * 3 + 0] = dx;
                dxv[p * 3 + 1] = dy;
                dxv[p * 3 + 2] = dz;
                bkt[p] = __fadd_rn(__fadd_rn(__fmul_rn(289.0f, bucket_base(dx)),
                                             __fmul_rn(17.0f, bucket_base(dy))),
                                   bucket_base(dz));
                dsc[p] = (float)((blj[p] >> 1) - sci);
                msk[p] = 1.0f;
            } else {
                dxv[p * 3 + 0] = 0.0f; dxv[p * 3 + 1] = 0.0f; dxv[p * 3 + 2] = 0.0f;
                bkt[p] = 0.0f; dsc[p] = 0.0f; msk[p] = 0.0f;
            }
        }

        // ensure TMA from iter k-2 has finished READING this buffer
        if (t == 0 && k >= 2) {
            asm volatile("cp.async.bulk.wait_group.read 1;" ::: "memory");
        }
        __syncthreads();

        // stage to SMEM (layout mirrors the global slices)
        float4* sdx = reinterpret_cast<float4*>(&sb[t * 12]);
        sdx[0] = make_float4(dxv[0], dxv[1], dxv[2],  dxv[3]);
        sdx[1] = make_float4(dxv[4], dxv[5], dxv[6],  dxv[7]);
        sdx[2] = make_float4(dxv[8], dxv[9], dxv[10], dxv[11]);
        *reinterpret_cast<float4*>(&sb[3 * JTILE + t * 4]) =
            make_float4(bkt[0], bkt[1], bkt[2], bkt[3]);
        *reinterpret_cast<float4*>(&sb[4 * JTILE + t * 4]) =
            make_float4(dsc[0], dsc[1], dsc[2], dsc[3]);
        *reinterpret_cast<float4*>(&sb[5 * JTILE + t * 4]) =
            make_float4(msk[0], msk[1], msk[2], msk[3]);

        __syncthreads();

        // issue bulk async drain of this tile (overlaps next iteration)
        if (t == 0) {
            asm volatile("fence.proxy.async.shared::cta;" ::: "memory");

            const size_t row = (size_t)i * N + (size_t)jbase;
            float* g_dx = out + row * 3;
            float* g_bk = out + 3 * NN + row;
            float* g_ds = out + 4 * NN + row;
            float* g_mk = out + 5 * NN + row;

            const unsigned bytes1 = JTILE * 4u;   // 4 KB
            const unsigned bytes3 = bytes1 * 3u;  // 12 KB

            asm volatile("cp.async.bulk.global.shared::cta.bulk_group [%0], [%1], %2;"
                         :: "l"(g_dx), "r"(smem_u32(&sb[0])), "r"(bytes3) : "memory");
            asm volatile("cp.async.bulk.global.shared::cta.bulk_group [%0], [%1], %2;"
                         :: "l"(g_bk), "r"(smem_u32(&sb[3 * JTILE])), "r"(bytes1) : "memory");
            asm volatile("cp.async.bulk.global.shared::cta.bulk_group [%0], [%1], %2;"
                         :: "l"(g_ds), "r"(smem_u32(&sb[4 * JTILE])), "r"(bytes1) : "memory");
            asm volatile("cp.async.bulk.global.shared::cta.bulk_group [%0], [%1], %2;"
                         :: "l"(g_mk), "r"(smem_u32(&sb[5 * JTILE])), "r"(bytes1) : "memory");
            asm volatile("cp.async.bulk.commit_group;" ::: "memory");
        }
    }

    // drain everything before SMEM is deallocated (block exit)
    if (t == 0) {
        asm volatile("cp.async.bulk.wait_group 0;" ::: "memory");
    }
    __syncthreads();
}

extern "C" void kernel_launch(void* const* d_in, const int* in_sizes, int n_in,
                              void* d_out, int out_size) {
    const float* xyz  = (const float*)d_in[0];   // [N,3] f32
    const int*   grid = (const int*)d_in[1];     // [N,5] i32
    float* out = (float*)d_out;

    const int N = in_sizes[0] / 3;               // 3072 (divisible by JTILE, ITERS)

    dim3 block(NTHREADS, 1, 1);
    dim3 gridDim(N / JTILE, N / ITERS, 1);       // 3 x 192 = 576 blocks = one wave
    pair_kernel<<<gridDim, block>>>(xyz, grid, out, N);
}

// round 17
// speedup vs baseline: 1.0156x; 1.0156x over previous
#include <cuda_runtime.h>
#include <math.h>

#define LOG8 2.0794415416798357f
#define NTHREADS 256
#define JTILE 1024   // j-elements per block (256 threads x 4)
#define ITERS 16     // i-rows per block

// SMEM staging tile (floats): [dxyz: 3*JTILE][bkt: JTILE][dsc: JTILE][msk: JTILE]
#define TILE_F (6 * JTILE)   // 6144 floats = 24 KB

__device__ __forceinline__ float bucket_base(float d) {
    float x  = d * 2.0f;              // d / RES, exact
    float ax = fabsf(x);
    float r;
    if (ax <= 2.0f) {
        r = rintf(x);                 // jnp.round = half-to-even
    } else {
        float lr  = __fdiv_rn(logf(__fmul_rn(ax, 0.5f)), LOG8);
        float sup = fminf(rintf(__fsub_rn(2.0f, __fmul_rn(6.0f, lr))), 8.0f);
        r = (x > 0.0f) ? sup : -sup;
    }
    return 8.0f + r;
}

__device__ __forceinline__ unsigned smem_u32(const void* p) {
    return (unsigned)__cvta_generic_to_shared(p);
}

__global__ __launch_bounds__(NTHREADS)
void pair_kernel(const float* __restrict__ xyz, const int* __restrict__ grid,
                 float* __restrict__ out, int N) {
    __shared__ float  sbuf[2][TILE_F];    // 2 x 24 KB staging (prologue scratch too)
    __shared__ float4 s_ipt[ITERS];       // packed i-rows: x,y,z,w1bits
    __shared__ int    s_iw2[ITERS];       // packed i-rows: w2

    const int t     = threadIdx.x;
    const int jbase = blockIdx.x * JTILE;
    const int i0    = blockIdx.y * ITERS;

    // ========= PROLOGUE: coalesced raw staging + pack (replaces pack_kernel) =========
    {
        // raw xyz of j-tile: JTILE*3 floats = 12 KB -> sbuf[0]
        const float4* gx = reinterpret_cast<const float4*>(xyz + (size_t)jbase * 3);
        float4* sx = reinterpret_cast<float4*>(&sbuf[0][0]);
#pragma unroll
        for (int q = 0; q < (JTILE * 3 / 4) / NTHREADS; q++)   // 3 iters
            sx[t + q * NTHREADS] = __ldg(gx + t + q * NTHREADS);

        // raw grid of j-tile: JTILE*5 ints = 20 KB -> sbuf[1]
        const int4* gg = reinterpret_cast<const int4*>(grid + (size_t)jbase * 5);
        int4* sg = reinterpret_cast<int4*>(&sbuf[1][0]);
#pragma unroll
        for (int q = 0; q < (JTILE * 5 / 4) / NTHREADS; q++)   // 5 iters
            sg[t + q * NTHREADS] = __ldg(gg + t + q * NTHREADS);

        // pack the block's 16 i-rows (tiny, scalar)
        if (t < ITERS) {
            const int i = i0 + t;
            const float x = __ldg(xyz + (size_t)i * 3 + 0);
            const float y = __ldg(xyz + (size_t)i * 3 + 1);
            const float z = __ldg(xyz + (size_t)i * 3 + 2);
            const int b  = __ldg(grid + (size_t)i * 5 + 0);
            const int bl = __ldg(grid + (size_t)i * 5 + 1);
            const int c0 = __ldg(grid + (size_t)i * 5 + 2);
            const int c1 = __ldg(grid + (size_t)i * 5 + 3);
            const int c2 = __ldg(grid + (size_t)i * 5 + 4);
            const int cx = (int)ceilf(__fdiv_rn(x, 3.0f));
            const int cy = (int)ceilf(__fdiv_rn(y, 3.0f));
            s_ipt[t] = make_float4(x, y, z,
                                   __int_as_float((bl << 24) | (c2 << 16) | (c1 << 8) | c0));
            s_iw2[t] = (b << 16) | (cy << 8) | cx;
        }
    }
    __syncthreads();

    // pack this thread's 4 j-points from SMEM into registers (once per block)
    float qjx[4], qjy[4], qjz[4];
    int w1j[4], w2j[4], blj[4];
    {
        const float* sx = &sbuf[0][0];
        const int*   sg = reinterpret_cast<const int*>(&sbuf[1][0]);
#pragma unroll
        for (int p = 0; p < 4; p++) {
            const int jl = t * 4 + p;
            qjx[p] = sx[jl * 3 + 0];
            qjy[p] = sx[jl * 3 + 1];
            qjz[p] = sx[jl * 3 + 2];
            const int b  = sg[jl * 5 + 0];
            const int bl = sg[jl * 5 + 1];
            const int c0 = sg[jl * 5 + 2];
            const int c1 = sg[jl * 5 + 3];
            const int c2 = sg[jl * 5 + 4];
            const int cx = (int)ceilf(__fdiv_rn(qjx[p], 3.0f));
            const int cy = (int)ceilf(__fdiv_rn(qjy[p], 3.0f));
            w1j[p] = (bl << 24) | (c2 << 16) | (c1 << 8) | c0;
            w2j[p] = (b << 16) | (cy << 8) | cx;
            blj[p] = bl;
        }
    }
    __syncthreads();   // raw staging consumed; buffers free for the main loop

    // ================= MAIN LOOP (identical to R8 best) =================
    const size_t NN = (size_t)N * (size_t)N;

    for (int k = 0; k < ITERS; k++) {
        const int i = i0 + k;
        float* sb = sbuf[k & 1];

        // per-i data: LDS broadcast
        const float4 qi  = s_ipt[k];
        const int    w1i = __float_as_int(qi.w);
        const int    w2i = s_iw2[k];
        const int    bli = ((unsigned)w1i) >> 24;
        const int    sci = bli >> 1;

        float dxv[12];
        float bkt[4], dsc[4], msk[4];

#pragma unroll
        for (int p = 0; p < 4; p++) {
            const float dx = qi.x - qjx[p];
            const float dy = qi.y - qjy[p];
            const float dz = qi.z - qjz[p];

            const unsigned d1 = __vabsdiffu4(w1i, w1j[p]);  // [c0d,c1d,c2d,bld]
            const unsigned d2 = __vabsdiffu4(w2i, w2j[p]);  // [cxd,cyd,bd,0]

            bool m = ((d2 & 0x00FF0000u) == 0u) && (bli <= blj[p]);
            if (m) {
                const bool fk = (d1 & 0xFFFEFEFEu) == 0u;
                if (!fk) {
                    const bool kc = (d2 & 0x0000FEFEu) == 0u;
                    const float r2 = __fadd_rn(__fadd_rn(__fmul_rn(dx, dx),
                                                         __fmul_rn(dy, dy)),
                                               __fmul_rn(dz, dz));
                    m = kc && (r2 <= 9.0f);
                }
            }

            if (m) {
                dxv[p * 3 + 0] = dx;
                dxv[p * 3 + 1] = dy;
                dxv[p * 3 + 2] = dz;
                bkt[p] = __fadd_rn(__fadd_rn(__fmul_rn(289.0f, bucket_base(dx)),
                                             __fmul_rn(17.0f, bucket_base(dy))),
                                   bucket_base(dz));
                dsc[p] = (float)((blj[p] >> 1) - sci);
                msk[p] = 1.0f;
            } else {
                dxv[p * 3 + 0] = 0.0f; dxv[p * 3 + 1] = 0.0f; dxv[p * 3 + 2] = 0.0f;
                bkt[p] = 0.0f; dsc[p] = 0.0f; msk[p] = 0.0f;
            }
        }

        // ensure TMA from iter k-2 has finished READING this buffer
        if (t == 0 && k >= 2) {
            asm volatile("cp.async.bulk.wait_group.read 1;" ::: "memory");
        }
        __syncthreads();

        // stage to SMEM (layout mirrors the global slices)
        float4* sdx = reinterpret_cast<float4*>(&sb[t * 12]);
        sdx[0] = make_float4(dxv[0], dxv[1], dxv[2],  dxv[3]);
        sdx[1] = make_float4(dxv[4], dxv[5], dxv[6],  dxv[7]);
        sdx[2] = make_float4(dxv[8], dxv[9], dxv[10], dxv[11]);
        *reinterpret_cast<float4*>(&sb[3 * JTILE + t * 4]) =
            make_float4(bkt[0], bkt[1], bkt[2], bkt[3]);
        *reinterpret_cast<float4*>(&sb[4 * JTILE + t * 4]) =
            make_float4(dsc[0], dsc[1], dsc[2], dsc[3]);
        *reinterpret_cast<float4*>(&sb[5 * JTILE + t * 4]) =
            make_float4(msk[0], msk[1], msk[2], msk[3]);

        __syncthreads();

        // issue bulk async drain of this tile (overlaps next iteration)
        if (t == 0) {
            asm volatile("fence.proxy.async.shared::cta;" ::: "memory");

            const size_t row = (size_t)i * N + (size_t)jbase;
            float* g_dx = out + row * 3;
            float* g_bk = out + 3 * NN + row;
            float* g_ds = out + 4 * NN + row;
            float* g_mk = out + 5 * NN + row;

            const unsigned bytes1 = JTILE * 4u;   // 4 KB
            const unsigned bytes3 = bytes1 * 3u;  // 12 KB

            asm volatile("cp.async.bulk.global.shared::cta.bulk_group [%0], [%1], %2;"
                         :: "l"(g_dx), "r"(smem_u32(&sb[0])), "r"(bytes3) : "memory");
            asm volatile("cp.async.bulk.global.shared::cta.bulk_group [%0], [%1], %2;"
                         :: "l"(g_bk), "r"(smem_u32(&sb[3 * JTILE])), "r"(bytes1) : "memory");
            asm volatile("cp.async.bulk.global.shared::cta.bulk_group [%0], [%1], %2;"
                         :: "l"(g_ds), "r"(smem_u32(&sb[4 * JTILE])), "r"(bytes1) : "memory");
            asm volatile("cp.async.bulk.global.shared::cta.bulk_group [%0], [%1], %2;"
                         :: "l"(g_mk), "r"(smem_u32(&sb[5 * JTILE])), "r"(bytes1) : "memory");
            asm volatile("cp.async.bulk.commit_group;" ::: "memory");
        }
    }

    // drain everything before SMEM is deallocated (block exit)
    if (t == 0) {
        asm volatile("cp.async.bulk.wait_group 0;" ::: "memory");
    }
    __syncthreads();
}

extern "C" void kernel_launch(void* const* d_in, const int* in_sizes, int n_in,
                              void* d_out, int out_size) {
    const float* xyz  = (const float*)d_in[0];   // [N,3] f32
    const int*   grid = (const int*)d_in[1];     // [N,5] i32
    float* out = (float*)d_out;

    const int N = in_sizes[0] / 3;               // 3072 (divisible by JTILE, ITERS)

    dim3 block(NTHREADS, 1, 1);
    dim3 gridDim(N / JTILE, N / ITERS, 1);       // 3 x 192 = 576 blocks = one wave
    pair_kernel<<<gridDim, block>>>(xyz, grid, out, N);
}